// round 14
// baseline (speedup 1.0000x reference)
#include <cuda_runtime.h>
#include <cuda_bf16.h>
#include <cstdint>
#include <cstddef>

// ---------------------------------------------------------------------------
// Problem constants
// ---------------------------------------------------------------------------
#define BATCH   256
#define NPTS    1024
#define HID     256
#define ACT     6
#define GRU_BLOCKS 128

// device scratch
__device__ float g_feat[BATCH * 512];
__device__ float g_gruh[BATCH * HID];
__device__ float g_WhhT[HID * 768];
__device__ unsigned g_W3tf[8 * 128 * 64];    // tf32 image, [chunk8][k][n64]
__device__ unsigned g_W2tf[64 * 128];        // tf32 image of W2 [k][j]
// GRU pair-exchange payload: [parity][block][4*384 gh + 16 x] + flags
__device__ float g_pay[2][GRU_BLOCKS][1552];
__device__ int   g_flag[GRU_BLOCKS];

// ---------------------------------------------------------------------------
// helpers
// ---------------------------------------------------------------------------
__device__ __forceinline__ unsigned f2tf(float x) {
    unsigned u; asm("cvt.rna.tf32.f32 %0, %1;" : "=r"(u) : "f"(x)); return u;
}

__device__ __forceinline__ void mma_tf32(float* d, const unsigned* a, const unsigned* b) {
    asm volatile(
        "mma.sync.aligned.m16n8k8.row.col.f32.tf32.tf32.f32 "
        "{%0,%1,%2,%3}, {%4,%5,%6,%7}, {%8,%9}, {%0,%1,%2,%3};\n"
        : "+f"(d[0]), "+f"(d[1]), "+f"(d[2]), "+f"(d[3])
        : "r"(a[0]), "r"(a[1]), "r"(a[2]), "r"(a[3]), "r"(b[0]), "r"(b[1]));
}

__device__ __forceinline__ void cp16(uint32_t dst_smem, const void* src) {
    asm volatile("cp.async.cg.shared.global [%0], [%1], 16;" :: "r"(dst_smem), "l"(src));
}
#define CP_COMMIT() asm volatile("cp.async.commit_group;" ::: "memory")
#define CP_WAIT0()  asm volatile("cp.async.wait_group 0;" ::: "memory")
#define BAR_A() asm volatile("bar.sync 1, 384;" ::: "memory")
#define BAR_B() asm volatile("bar.sync 2, 256;" ::: "memory")

__device__ __forceinline__ float sigf(float x) { return 1.f / (1.f + __expf(-x)); }
__device__ __forceinline__ float tanhfast(float x) { return 2.f / (1.f + __expf(-2.f * x)) - 1.f; }

// ---------------------------------------------------------------------------
// fused prep kernel: zero_feat | Whh transpose | W3 tf32 | W2 tf32 | flags
// ---------------------------------------------------------------------------
__global__ void prep_kernel(const float* __restrict__ Whh,
                            const float* __restrict__ w3,
                            const float* __restrict__ w2) {
    int idx = blockIdx.x * 256 + threadIdx.x;
    if (idx < 131072) { g_feat[idx] = 0.f; return; }
    idx -= 131072;
    if (idx < 196608) {
        int k = idx / 768, j = idx - k * 768;
        g_WhhT[idx] = Whh[j * 256 + k];
        return;
    }
    idx -= 196608;
    if (idx < 65536) {
        int c = idx >> 13;
        int r = idx & 8191;
        int k = r >> 6, n = r & 63;
        g_W3tf[idx] = f2tf(w3[(size_t)k * 512 + c * 64 + n]);
        return;
    }
    idx -= 65536;
    if (idx < 8192) { g_W2tf[idx] = f2tf(w2[idx]); return; }
    idx -= 8192;
    if (idx < GRU_BLOCKS) g_flag[idx] = 0;
}

// ---------------------------------------------------------------------------
// Fused PointNet encoder (identical to R13 passing version)
// ---------------------------------------------------------------------------
#define ENC_HP_LD 132
#define ENC_B2_LD 136
#define ENC_SW_LD 72
#define ENC_A2_LD 68
#define ENC_SMEM_FLOATS (16896 + 9216 + 512)

__global__ void __launch_bounds__(512, 2) enc_kernel(
    const float* __restrict__ data,
    const float* __restrict__ w1, const float* __restrict__ b1,
    const float* __restrict__ b2, const float* __restrict__ b3)
{
    extern __shared__ float sm[];
    float* Hp   = sm;
    float* buf  = sm + 16896;
    float* sRed = sm + 16896 + 9216;
    __shared__ float sPts[128 * 3];

    const int tid   = threadIdx.x;
    const int b     = blockIdx.y;
    const int chunk = blockIdx.x;

    unsigned* A2 = (unsigned*)sm;
    unsigned* B2 = (unsigned*)buf;
    uint32_t bufaddr = (uint32_t)__cvta_generic_to_shared(buf);

    const float* dptr = data + (size_t)(b * NPTS + chunk * 128) * 3;
    if (tid < 384) sPts[tid] = dptr[tid];
    for (int idx = tid; idx < 8192; idx += 512) {
        int k = idx >> 7, j = idx & 127;
        B2[k * ENC_B2_LD + j] = g_W2tf[idx];
    }
    __syncthreads();

    #pragma unroll
    for (int it = 0; it < 16; ++it) {
        int idx = tid + it * 512;
        int k = idx >> 7, i = idx & 127;
        float v = b1[k] + sPts[i*3] * w1[k] + sPts[i*3+1] * w1[64 + k] + sPts[i*3+2] * w1[128 + k];
        A2[i * ENC_A2_LD + k] = f2tf(fmaxf(v, 0.f));
    }
    __syncthreads();

    const int lane = tid & 31, wrp = tid >> 5;
    const int qp = lane >> 2, rr = lane & 3;
    unsigned* Hpu = (unsigned*)Hp;

    {
        const int wm = wrp & 3, wn = wrp >> 2;
        float acc[2][4][4];
        #pragma unroll
        for (int mt = 0; mt < 2; ++mt)
            #pragma unroll
            for (int nt = 0; nt < 4; ++nt)
                #pragma unroll
                for (int q = 0; q < 4; ++q) acc[mt][nt][q] = 0.f;

        #pragma unroll 2
        for (int ks = 0; ks < 8; ++ks) {
            int k0 = ks * 8;
            unsigned af[2][4];
            #pragma unroll
            for (int mt = 0; mt < 2; ++mt) {
                int r0 = wm * 32 + mt * 16 + qp;
                af[mt][0] = A2[r0 * ENC_A2_LD + k0 + rr];
                af[mt][1] = A2[(r0 + 8) * ENC_A2_LD + k0 + rr];
                af[mt][2] = A2[r0 * ENC_A2_LD + k0 + rr + 4];
                af[mt][3] = A2[(r0 + 8) * ENC_A2_LD + k0 + rr + 4];
            }
            unsigned bf[4][2];
            #pragma unroll
            for (int nt = 0; nt < 4; ++nt) {
                int n = wn * 32 + nt * 8 + qp;
                bf[nt][0] = B2[(k0 + rr) * ENC_B2_LD + n];
                bf[nt][1] = B2[(k0 + 4 + rr) * ENC_B2_LD + n];
            }
            #pragma unroll
            for (int mt = 0; mt < 2; ++mt)
                #pragma unroll
                for (int nt = 0; nt < 4; ++nt)
                    mma_tf32(acc[mt][nt], af[mt], bf[nt]);
        }
        __syncthreads();

        #pragma unroll
        for (int mt = 0; mt < 2; ++mt) {
            int r0 = wm * 32 + mt * 16 + qp;
            #pragma unroll
            for (int nt = 0; nt < 4; ++nt) {
                int c0 = wn * 32 + nt * 8 + 2 * rr;
                float bv0 = b2[c0], bv1 = b2[c0 + 1];
                float* d = acc[mt][nt];
                unsigned u0 = f2tf(fmaxf(d[0] + bv0, 0.f));
                unsigned u1 = f2tf(fmaxf(d[1] + bv1, 0.f));
                unsigned u2 = f2tf(fmaxf(d[2] + bv0, 0.f));
                unsigned u3 = f2tf(fmaxf(d[3] + bv1, 0.f));
                *(uint2*)(Hpu + r0 * ENC_HP_LD + c0)       = make_uint2(u0, u1);
                *(uint2*)(Hpu + (r0 + 8) * ENC_HP_LD + c0) = make_uint2(u2, u3);
            }
        }
    }
    __syncthreads();

    const int wm3 = wrp & 7, wn3 = wrp >> 3;
    unsigned* sWu = (unsigned*)buf;

    for (int nc = 0; nc < 8; ++nc) {
        {
            const float* src = (const float*)(g_W3tf + nc * 8192);
            for (int i = tid * 4; i < 8192; i += 2048) {
                int k = i >> 6, n = i & 63;
                cp16(bufaddr + (k * ENC_SW_LD + n) * 4, src + i);
            }
            CP_COMMIT();
            CP_WAIT0();
        }
        __syncthreads();

        float acc[4][4];
        #pragma unroll
        for (int nt = 0; nt < 4; ++nt)
            #pragma unroll
            for (int q = 0; q < 4; ++q) acc[nt][q] = 0.f;

        #pragma unroll 2
        for (int ks = 0; ks < 16; ++ks) {
            int k0 = ks * 8;
            unsigned af[4];
            {
                int r0 = wm3 * 16 + qp;
                af[0] = Hpu[r0 * ENC_HP_LD + k0 + rr];
                af[1] = Hpu[(r0 + 8) * ENC_HP_LD + k0 + rr];
                af[2] = Hpu[r0 * ENC_HP_LD + k0 + rr + 4];
                af[3] = Hpu[(r0 + 8) * ENC_HP_LD + k0 + rr + 4];
            }
            unsigned bf[4][2];
            #pragma unroll
            for (int nt = 0; nt < 4; ++nt) {
                int n = wn3 * 32 + nt * 8 + qp;
                bf[nt][0] = sWu[(k0 + rr) * ENC_SW_LD + n];
                bf[nt][1] = sWu[(k0 + 4 + rr) * ENC_SW_LD + n];
            }
            #pragma unroll
            for (int nt = 0; nt < 4; ++nt)
                mma_tf32(acc[nt], af, bf[nt]);
        }

        #pragma unroll
        for (int nt = 0; nt < 4; ++nt) {
            int n = wn3 * 32 + nt * 8 + 2 * rr;
            float bv0 = b3[nc * 64 + n];
            float bv1 = b3[nc * 64 + n + 1];
            float* d = acc[nt];
            float m0 = fmaxf(fmaxf(d[0] + bv0, d[2] + bv0), 0.f);
            float m1 = fmaxf(fmaxf(d[1] + bv1, d[3] + bv1), 0.f);
            #pragma unroll
            for (int s = 4; s < 32; s <<= 1) {
                m0 = fmaxf(m0, __shfl_xor_sync(0xffffffffu, m0, s));
                m1 = fmaxf(m1, __shfl_xor_sync(0xffffffffu, m1, s));
            }
            if (qp == 0) {
                sRed[wm3 * 64 + n]     = m0;
                sRed[wm3 * 64 + n + 1] = m1;
            }
        }
        __syncthreads();
        if (tid < 64) {
            float m = sRed[tid];
            #pragma unroll
            for (int w = 1; w < 8; ++w) m = fmaxf(m, sRed[w * 64 + tid]);
            atomicMax((int*)&g_feat[b * 512 + nc * 64 + tid], __float_as_int(m));
        }
    }
}

// ---------------------------------------------------------------------------
// Head MLP (identical to R13 passing version)
// ---------------------------------------------------------------------------
__global__ void __launch_bounds__(512) head_kernel(
    const float* __restrict__ w1, const float* __restrict__ b1,
    const float* __restrict__ w2, const float* __restrict__ b2,
    const float* __restrict__ w3, const float* __restrict__ b3)
{
    __shared__ float sh[512];
    __shared__ float pp[512];
    __shared__ float s1[256];
    __shared__ float s2[128];
    int b = blockIdx.x, tid = threadIdx.x;
    sh[tid] = g_feat[b * 512 + tid];
    __syncthreads();
    {
        int j = tid & 255, half = tid >> 8, k0 = half * 256;
        const float* wp = w1 + (size_t)k0 * 256 + j;
        float a0 = 0, a1 = 0, a2 = 0, a3 = 0;
        #pragma unroll 8
        for (int k = 0; k < 256; k += 4) {
            a0 += sh[k0 + k]     * wp[(size_t)k * 256];
            a1 += sh[k0 + k + 1] * wp[(size_t)(k + 1) * 256];
            a2 += sh[k0 + k + 2] * wp[(size_t)(k + 2) * 256];
            a3 += sh[k0 + k + 3] * wp[(size_t)(k + 3) * 256];
        }
        pp[tid] = (a0 + a1) + (a2 + a3);
    }
    __syncthreads();
    if (tid < 256) s1[tid] = fmaxf(b1[tid] + pp[tid] + pp[tid + 256], 0.f);
    __syncthreads();
    {
        int j = tid & 127, q = tid >> 7, k0 = q * 64;
        const float* wp = w2 + k0 * 128 + j;
        float a0 = 0, a1 = 0;
        #pragma unroll 8
        for (int k = 0; k < 64; k += 2) {
            a0 += s1[k0 + k]     * wp[k * 128];
            a1 += s1[k0 + k + 1] * wp[(k + 1) * 128];
        }
        pp[tid] = a0 + a1;
    }
    __syncthreads();
    if (tid < 128) s2[tid] = fmaxf(b2[tid] + pp[tid] + pp[tid + 128] + pp[tid + 256] + pp[tid + 384], 0.f);
    __syncthreads();
    {
        int j = tid & 255, half = tid >> 8, k0 = half * 64;
        const float* wp = w3 + k0 * 256 + j;
        float a0 = 0, a1 = 0;
        #pragma unroll 8
        for (int k = 0; k < 64; k += 2) {
            a0 += s2[k0 + k]     * wp[k * 256];
            a1 += s2[k0 + k + 1] * wp[(k + 1) * 256];
        }
        pp[tid] = a0 + a1;
    }
    __syncthreads();
    if (tid < 256) g_gruh[b * HID + tid] = b3[tid] + pp[tid] + pp[tid + 256];
}

// ---------------------------------------------------------------------------
// GRU rollout v9: pair topology + warp specialization.
//  Group A (tid<384): GEMM (96 jg x 4 kslices of 64) + reduce + publish.
//  Group B (384<=tid<640): PREVIOUS step's out-MLP, overlapped with A's GEMM.
//  Remaining 128 threads idle during overlap, join gather/gates.
// ---------------------------------------------------------------------------
#define GRU_SMEM_FLOATS 38184

__global__ void __launch_bounds__(768) gru_kernel(
    const float* __restrict__ Wih, const float* __restrict__ bih, const float* __restrict__ bhh,
    const float* __restrict__ ow1, const float* __restrict__ ob1,
    const float* __restrict__ ow2, const float* __restrict__ ob2,
    const float* __restrict__ ow3, const float* __restrict__ ob3,
    const int* __restrict__ horizon_p, float* __restrict__ out, int out_size)
{
    extern __shared__ float sm[];
    float* s_Wih  = sm;                   // 4608
    float* s_bih  = s_Wih + 4608;         // 768
    float* s_bhh  = s_bih + 768;          // 768
    float* s_w1   = s_bhh + 768;          // 16384
    float* s_w2   = s_w1 + 16384;         // 4096
    float* s_w3   = s_w2 + 4096;          // 384
    float* s_b1   = s_w3 + 384;           // 64
    float* s_b2   = s_b1 + 64;            // 64
    float* s_b3   = s_b2 + 64;            // 8
    float* s_h    = s_b3 + 8;             // 1024
    float* s_x    = s_h + 1024;           // 32
    float* s_gh   = s_x + 32;             // 3072
    float* s_part = s_gh + 3072;          // 6144 (4 slices x 96 jg x 16)
    float* s_p1   = s_part + 6144;        // 512
    float* s_o1   = s_p1 + 512;           // 128
    float* s_o2   = s_o1 + 128;           // 128

    const int tid     = threadIdx.x;
    const int bid     = blockIdx.x;
    const int pairid  = bid >> 1;
    const int half    = bid & 1;
    const int partner = bid ^ 1;
    const int b0      = pairid * 4;

    for (int i = tid; i < 4608;  i += 768) s_Wih[i] = Wih[i];
    for (int i = tid; i < 768;   i += 768) { s_bih[i] = bih[i]; s_bhh[i] = bhh[i]; }
    for (int i = tid; i < 16384; i += 768) s_w1[i] = ow1[i];
    for (int i = tid; i < 4096;  i += 768) s_w2[i] = ow2[i];
    if (tid < 384) s_w3[tid] = ow3[tid];
    if (tid < 64) { s_b1[tid] = ob1[tid]; s_b2[tid] = ob2[tid]; }
    if (tid < 6)  s_b3[tid] = ob3[tid];
    for (int i = tid; i < 1024; i += 768) {
        int r = i >> 8, k = i & 255;
        s_h[i] = g_gruh[(b0 + r) * HID + k];
    }
    if (tid < 32) s_x[tid] = 0.f;
    __syncthreads();

    int T = 50;
    if (horizon_p) {
        int v = *horizon_p;
        if (v > 0 && v <= 1000000) T = v;
        else {
            float fv = __int_as_float(v);
            if (fv > 0.f && fv <= 1000000.f) T = (int)fv;
        }
    }
    const int off2 = out_size >> 1;

    // Group A mapping
    const int jg   = tid % 96;
    const int ks   = tid / 96;            // 0..3 for tid<384
    const int k0   = ks * 64;
    const int jcol = half * 384 + jg * 4;
    const float* Wcol = g_WhhT + jcol;

    for (int t = 0; t < T; ++t) {
        const int par = t & 1;
        float* pay_out = &g_pay[par][bid][0];
        const float* pay_in = &g_pay[par][partner][0];

        if (tid < 384) {
            // ---- GEMM: 4 rows x 4 cols over 64 k ----
            float acc[4][4];
            #pragma unroll
            for (int r = 0; r < 4; ++r)
                #pragma unroll
                for (int c = 0; c < 4; ++c) acc[r][c] = 0.f;

            #pragma unroll 2
            for (int kk = 0; kk < 64; kk += 4) {
                float4 h0 = *(float4*)&s_h[0 * 256 + k0 + kk];
                float4 h1 = *(float4*)&s_h[1 * 256 + k0 + kk];
                float4 h2 = *(float4*)&s_h[2 * 256 + k0 + kk];
                float4 h3 = *(float4*)&s_h[3 * 256 + k0 + kk];
                const float* wb = Wcol + (size_t)(k0 + kk) * 768;
                #pragma unroll
                for (int q = 0; q < 4; ++q) {
                    float4 w = *(const float4*)(wb + (size_t)q * 768);
                    float a0 = (q == 0) ? h0.x : (q == 1) ? h0.y : (q == 2) ? h0.z : h0.w;
                    float a1 = (q == 0) ? h1.x : (q == 1) ? h1.y : (q == 2) ? h1.z : h1.w;
                    float a2 = (q == 0) ? h2.x : (q == 1) ? h2.y : (q == 2) ? h2.z : h2.w;
                    float a3 = (q == 0) ? h3.x : (q == 1) ? h3.y : (q == 2) ? h3.z : h3.w;
                    acc[0][0] += a0*w.x; acc[0][1] += a0*w.y; acc[0][2] += a0*w.z; acc[0][3] += a0*w.w;
                    acc[1][0] += a1*w.x; acc[1][1] += a1*w.y; acc[1][2] += a1*w.z; acc[1][3] += a1*w.w;
                    acc[2][0] += a2*w.x; acc[2][1] += a2*w.y; acc[2][2] += a2*w.z; acc[2][3] += a2*w.w;
                    acc[3][0] += a3*w.x; acc[3][1] += a3*w.y; acc[3][2] += a3*w.z; acc[3][3] += a3*w.w;
                }
            }
            {
                float* p = &s_part[(ks * 96 + jg) * 16];
                #pragma unroll
                for (int r = 0; r < 4; ++r)
                    *(float4*)(p + r * 4) = make_float4(acc[r][0], acc[r][1], acc[r][2], acc[r][3]);
            }
            BAR_A();
            {
                int jgR = tid % 96, rR = tid / 96;
                float4 s = make_float4(0.f, 0.f, 0.f, 0.f);
                #pragma unroll
                for (int s4 = 0; s4 < 4; ++s4) {
                    float4 v = *(float4*)&s_part[(s4 * 96 + jgR) * 16 + rR * 4];
                    s.x += v.x; s.y += v.y; s.z += v.z; s.w += v.w;
                }
                *(float4*)&s_gh[rR * 768 + half * 384 + jgR * 4] = s;
                *(float4*)&pay_out[rR * 384 + jgR * 4] = s;
            }
        } else if (tid < 640) {
            // ---- Group B: out-MLP for step t-1 (overlapped with A's GEMM) ----
            int tid2 = tid - 384;
            if (t == 0) {
                if (tid2 < 12) pay_out[1536 + tid2] = 0.f;
            } else {
                int kq = tid2 >> 6, j = tid2 & 63;
                {
                    const float* wp = s_w1 + (kq * 64) * 64 + j;
                    const float* h0 = s_h + (half * 2 + 0) * 256 + kq * 64;
                    const float* h1 = s_h + (half * 2 + 1) * 256 + kq * 64;
                    float a0 = 0.f, a1 = 0.f;
                    #pragma unroll 8
                    for (int k = 0; k < 64; ++k) {
                        float w = wp[k * 64];
                        a0 += h0[k] * w;
                        a1 += h1[k] * w;
                    }
                    s_p1[kq * 64 + j] = a0;
                    s_p1[256 + kq * 64 + j] = a1;
                }
                BAR_B();
                if (tid2 < 128) {
                    int rl = tid2 >> 6, jj = tid2 & 63;
                    const float* p = s_p1 + rl * 256 + jj;
                    s_o1[tid2] = fmaxf(s_b1[jj] + (p[0] + p[64]) + (p[128] + p[192]), 0.f);
                }
                BAR_B();
                if (tid2 < 128) {
                    int rl = tid2 >> 6, jj = tid2 & 63;
                    float a0 = 0, a1 = 0;
                    #pragma unroll 8
                    for (int k = 0; k < 64; k += 2) {
                        a0 += s_o1[rl*64 + k]     * s_w2[k * 64 + jj];
                        a1 += s_o1[rl*64 + k + 1] * s_w2[(k + 1) * 64 + jj];
                    }
                    s_o2[tid2] = fmaxf(s_b2[jj] + a0 + a1, 0.f);
                }
                BAR_B();
                if (tid2 < 12) {
                    int rl = tid2 / 6, a = tid2 % 6;
                    float d0 = 0, d1 = 0;
                    #pragma unroll 8
                    for (int k = 0; k < 64; k += 2) {
                        d0 += s_o2[rl*64 + k]     * s_w3[k * 6 + a];
                        d1 += s_o2[rl*64 + k + 1] * s_w3[(k + 1) * 6 + a];
                    }
                    float d = s_b3[a] + d0 + d1;
                    int rloc = half * 2 + rl;
                    float xn = s_x[rloc * 8 + a] + d;
                    s_x[rloc * 8 + a] = xn;
                    pay_out[1536 + tid2] = xn;
                    int b = b0 + rloc;
                    size_t o = ((size_t)b * T + (t - 1)) * 6 + a;
                    out[o] = d;
                    out[off2 + o] = xn;
                }
            }
        }
        __syncthreads();
        if (tid == 0) {
            asm volatile("fence.acq_rel.gpu;" ::: "memory");
            atomicExch(&g_flag[bid], t + 1);
            int v;
            do {
                asm volatile("ld.acquire.gpu.global.b32 %0, [%1];"
                             : "=r"(v) : "l"(&g_flag[partner]) : "memory");
            } while (v < t + 1);
        }
        __syncthreads();

        // ---- gather partner half into s_gh + partner x ----
        if (tid < 384) {
            int rr = tid / 96, off = (tid % 96) * 4;
            float4 v = __ldcg((const float4*)&pay_in[rr * 384 + off]);
            *(float4*)&s_gh[rr * 768 + (half ^ 1) * 384 + off] = v;
        }
        if (tid < 12) {
            int rl = tid / 6, a = tid % 6;
            s_x[((half ^ 1) * 2 + rl) * 8 + a] = __ldcg(&pay_in[1536 + tid]);
        }
        __syncthreads();

        // ---- gates + h update (all 4 rows) ----
        #pragma unroll
        for (int it = 0; it < 2; ++it) {
            int item = tid + it * 768;
            if (item < 1024) {
                int r = item >> 8, kk = item & 255;
                float x0 = s_x[r*8+0], x1 = s_x[r*8+1], x2 = s_x[r*8+2];
                float x3 = s_x[r*8+3], x4 = s_x[r*8+4], x5 = s_x[r*8+5];
                const float* wr = s_Wih + kk * 6;
                const float* wz = s_Wih + (256 + kk) * 6;
                const float* wn = s_Wih + (512 + kk) * 6;
                float gir = s_bih[kk]       + x0*wr[0]+x1*wr[1]+x2*wr[2]+x3*wr[3]+x4*wr[4]+x5*wr[5];
                float giz = s_bih[256 + kk] + x0*wz[0]+x1*wz[1]+x2*wz[2]+x3*wz[3]+x4*wz[4]+x5*wz[5];
                float gin = s_bih[512 + kk] + x0*wn[0]+x1*wn[1]+x2*wn[2]+x3*wn[3]+x4*wn[4]+x5*wn[5];
                float rr = sigf(gir + s_gh[r*768 + kk] + s_bhh[kk]);
                float zz = sigf(giz + s_gh[r*768 + 256 + kk] + s_bhh[256 + kk]);
                float nn = tanhfast(gin + rr * (s_gh[r*768 + 512 + kk] + s_bhh[512 + kk]));
                s_h[r*256 + kk] = (1.f - zz) * nn + zz * s_h[r*256 + kk];
            }
        }
        __syncthreads();
    }

    // ---- final out-MLP for step T-1 (all threads, classic path) ----
    if (tid < 512) {
        int rl = tid >> 8, kq = (tid >> 6) & 3, j = tid & 63;
        const float* hb = s_h + (half * 2 + rl) * 256 + kq * 64;
        const float* wp = s_w1 + (kq * 64) * 64 + j;
        float a0 = 0, a1 = 0;
        #pragma unroll 8
        for (int k = 0; k < 64; k += 2) {
            a0 += hb[k]     * wp[k * 64];
            a1 += hb[k + 1] * wp[(k + 1) * 64];
        }
        s_p1[(rl * 4 + kq) * 64 + j] = a0 + a1;
    }
    __syncthreads();
    if (tid < 128) {
        int rl = tid >> 6, j = tid & 63;
        const float* p = s_p1 + rl * 256 + j;
        s_o1[tid] = fmaxf(s_b1[j] + (p[0] + p[64]) + (p[128] + p[192]), 0.f);
    }
    __syncthreads();
    if (tid < 128) {
        int rl = tid >> 6, j = tid & 63;
        float a0 = 0, a1 = 0;
        #pragma unroll 8
        for (int k = 0; k < 64; k += 2) {
            a0 += s_o1[rl*64 + k]     * s_w2[k * 64 + j];
            a1 += s_o1[rl*64 + k + 1] * s_w2[(k + 1) * 64 + j];
        }
        s_o2[tid] = fmaxf(s_b2[j] + a0 + a1, 0.f);
    }
    __syncthreads();
    if (tid < 12) {
        int rl = tid / 6, a = tid % 6;
        float d0 = 0, d1 = 0;
        #pragma unroll 8
        for (int k = 0; k < 64; k += 2) {
            d0 += s_o2[rl*64 + k]     * s_w3[k * 6 + a];
            d1 += s_o2[rl*64 + k + 1] * s_w3[(k + 1) * 6 + a];
        }
        float d = s_b3[a] + d0 + d1;
        int rloc = half * 2 + rl;
        float xn = s_x[rloc * 8 + a] + d;
        int b = b0 + rloc;
        size_t o = ((size_t)b * T + (T - 1)) * 6 + a;
        out[o] = d;
        out[off2 + o] = xn;
    }
}

// ---------------------------------------------------------------------------
// launch
// ---------------------------------------------------------------------------
extern "C" void kernel_launch(void* const* d_in, const int* in_sizes, int n_in,
                              void* d_out, int out_size)
{
    int hpos = -1;
    for (int i = 0; i < n_in; ++i) if (in_sizes[i] == 1) hpos = i;

    const float* ins[23];
    int j = 0;
    for (int i = 0; i < n_in && j < 23; ++i) {
        if (i == hpos) continue;
        ins[j++] = (const float*)d_in[i];
    }
    const int* hp = (hpos >= 0) ? (const int*)d_in[hpos] : nullptr;

    // ins: 0 data | 1 enc_w1 2 enc_b1 3 enc_w2 4 enc_b2 5 enc_w3 6 enc_b3
    //      7 mlp_w1 8 mlp_b1 9 mlp_w2 10 mlp_b2 11 mlp_w3 12 mlp_b3
    //      13 W_ih 14 W_hh 15 b_ih 16 b_hh
    //      17 out_w1 18 out_b1 19 out_w2 20 out_b2 21 out_w3 22 out_b3

    const int enc_smem = ENC_SMEM_FLOATS * 4;
    const int gru_smem = GRU_SMEM_FLOATS * 4;
    cudaFuncSetAttribute(enc_kernel, cudaFuncAttributeMaxDynamicSharedMemorySize, enc_smem);
    cudaFuncSetAttribute(gru_kernel, cudaFuncAttributeMaxDynamicSharedMemorySize, gru_smem);

    prep_kernel<<<1569, 256>>>(ins[14], ins[5], ins[3]);
    enc_kernel<<<dim3(8, 256), 512, enc_smem>>>(ins[0], ins[1], ins[2], ins[4], ins[6]);
    head_kernel<<<256, 512>>>(ins[7], ins[8], ins[9], ins[10], ins[11], ins[12]);
    gru_kernel<<<GRU_BLOCKS, 768, gru_smem>>>(ins[13], ins[15], ins[16],
                                              ins[17], ins[18], ins[19], ins[20], ins[21], ins[22],
                                              hp, (float*)d_out, out_size);
}

// round 15
// speedup vs baseline: 1.1015x; 1.1015x over previous
#include <cuda_runtime.h>
#include <cuda_bf16.h>
#include <cstdint>
#include <cstddef>

// ---------------------------------------------------------------------------
// Problem constants
// ---------------------------------------------------------------------------
#define BATCH   256
#define NPTS    1024
#define HID     256
#define ACT     6
#define GRU_BLOCKS 128

// device scratch
__device__ float g_feat[BATCH * 512];
__device__ float g_gruh[BATCH * HID];
__device__ float g_WhhT[HID * 768];
__device__ unsigned g_W3tf[8 * 128 * 64];    // tf32 image, [chunk8][k][n64]
__device__ unsigned g_W2tf[64 * 128];        // tf32 image of W2 [k][j]
// GRU pair-exchange payload: [parity][block][4*384 gh + 12 x] + flags
__device__ float g_pay[2][GRU_BLOCKS][1552];
__device__ int   g_flag[GRU_BLOCKS];

// ---------------------------------------------------------------------------
// helpers
// ---------------------------------------------------------------------------
__device__ __forceinline__ unsigned f2tf(float x) {
    unsigned u; asm("cvt.rna.tf32.f32 %0, %1;" : "=r"(u) : "f"(x)); return u;
}

__device__ __forceinline__ void mma_tf32(float* d, const unsigned* a, const unsigned* b) {
    asm volatile(
        "mma.sync.aligned.m16n8k8.row.col.f32.tf32.tf32.f32 "
        "{%0,%1,%2,%3}, {%4,%5,%6,%7}, {%8,%9}, {%0,%1,%2,%3};\n"
        : "+f"(d[0]), "+f"(d[1]), "+f"(d[2]), "+f"(d[3])
        : "r"(a[0]), "r"(a[1]), "r"(a[2]), "r"(a[3]), "r"(b[0]), "r"(b[1]));
}

__device__ __forceinline__ void cp16(uint32_t dst_smem, const void* src) {
    asm volatile("cp.async.cg.shared.global [%0], [%1], 16;" :: "r"(dst_smem), "l"(src));
}
#define CP_COMMIT() asm volatile("cp.async.commit_group;" ::: "memory")
#define CP_WAIT0()  asm volatile("cp.async.wait_group 0;" ::: "memory")

__device__ __forceinline__ float sigf(float x) { return 1.f / (1.f + __expf(-x)); }
__device__ __forceinline__ float tanhfast(float x) { return 2.f / (1.f + __expf(-2.f * x)) - 1.f; }

// ---------------------------------------------------------------------------
// fused prep kernel: zero_feat | Whh transpose | W3 tf32 | W2 tf32 | flags
// ---------------------------------------------------------------------------
__global__ void prep_kernel(const float* __restrict__ Whh,
                            const float* __restrict__ w3,
                            const float* __restrict__ w2) {
    int idx = blockIdx.x * 256 + threadIdx.x;
    if (idx < 131072) { g_feat[idx] = 0.f; return; }
    idx -= 131072;
    if (idx < 196608) {
        int k = idx / 768, j = idx - k * 768;
        g_WhhT[idx] = Whh[j * 256 + k];
        return;
    }
    idx -= 196608;
    if (idx < 65536) {
        int c = idx >> 13;
        int r = idx & 8191;
        int k = r >> 6, n = r & 63;
        g_W3tf[idx] = f2tf(w3[(size_t)k * 512 + c * 64 + n]);
        return;
    }
    idx -= 65536;
    if (idx < 8192) { g_W2tf[idx] = f2tf(w2[idx]); return; }
    idx -= 8192;
    if (idx < GRU_BLOCKS) g_flag[idx] = 0;
}

// ---------------------------------------------------------------------------
// Fused PointNet encoder (identical to R13 passing version)
// ---------------------------------------------------------------------------
#define ENC_HP_LD 132
#define ENC_B2_LD 136
#define ENC_SW_LD 72
#define ENC_A2_LD 68
#define ENC_SMEM_FLOATS (16896 + 9216 + 512)

__global__ void __launch_bounds__(512, 2) enc_kernel(
    const float* __restrict__ data,
    const float* __restrict__ w1, const float* __restrict__ b1,
    const float* __restrict__ b2, const float* __restrict__ b3)
{
    extern __shared__ float sm[];
    float* Hp   = sm;
    float* buf  = sm + 16896;
    float* sRed = sm + 16896 + 9216;
    __shared__ float sPts[128 * 3];

    const int tid   = threadIdx.x;
    const int b     = blockIdx.y;
    const int chunk = blockIdx.x;

    unsigned* A2 = (unsigned*)sm;
    unsigned* B2 = (unsigned*)buf;
    uint32_t bufaddr = (uint32_t)__cvta_generic_to_shared(buf);

    const float* dptr = data + (size_t)(b * NPTS + chunk * 128) * 3;
    if (tid < 384) sPts[tid] = dptr[tid];
    for (int idx = tid; idx < 8192; idx += 512) {
        int k = idx >> 7, j = idx & 127;
        B2[k * ENC_B2_LD + j] = g_W2tf[idx];
    }
    __syncthreads();

    #pragma unroll
    for (int it = 0; it < 16; ++it) {
        int idx = tid + it * 512;
        int k = idx >> 7, i = idx & 127;
        float v = b1[k] + sPts[i*3] * w1[k] + sPts[i*3+1] * w1[64 + k] + sPts[i*3+2] * w1[128 + k];
        A2[i * ENC_A2_LD + k] = f2tf(fmaxf(v, 0.f));
    }
    __syncthreads();

    const int lane = tid & 31, wrp = tid >> 5;
    const int qp = lane >> 2, rr = lane & 3;
    unsigned* Hpu = (unsigned*)Hp;

    {
        const int wm = wrp & 3, wn = wrp >> 2;
        float acc[2][4][4];
        #pragma unroll
        for (int mt = 0; mt < 2; ++mt)
            #pragma unroll
            for (int nt = 0; nt < 4; ++nt)
                #pragma unroll
                for (int q = 0; q < 4; ++q) acc[mt][nt][q] = 0.f;

        #pragma unroll 2
        for (int ks = 0; ks < 8; ++ks) {
            int k0 = ks * 8;
            unsigned af[2][4];
            #pragma unroll
            for (int mt = 0; mt < 2; ++mt) {
                int r0 = wm * 32 + mt * 16 + qp;
                af[mt][0] = A2[r0 * ENC_A2_LD + k0 + rr];
                af[mt][1] = A2[(r0 + 8) * ENC_A2_LD + k0 + rr];
                af[mt][2] = A2[r0 * ENC_A2_LD + k0 + rr + 4];
                af[mt][3] = A2[(r0 + 8) * ENC_A2_LD + k0 + rr + 4];
            }
            unsigned bf[4][2];
            #pragma unroll
            for (int nt = 0; nt < 4; ++nt) {
                int n = wn * 32 + nt * 8 + qp;
                bf[nt][0] = B2[(k0 + rr) * ENC_B2_LD + n];
                bf[nt][1] = B2[(k0 + 4 + rr) * ENC_B2_LD + n];
            }
            #pragma unroll
            for (int mt = 0; mt < 2; ++mt)
                #pragma unroll
                for (int nt = 0; nt < 4; ++nt)
                    mma_tf32(acc[mt][nt], af[mt], bf[nt]);
        }
        __syncthreads();

        #pragma unroll
        for (int mt = 0; mt < 2; ++mt) {
            int r0 = wm * 32 + mt * 16 + qp;
            #pragma unroll
            for (int nt = 0; nt < 4; ++nt) {
                int c0 = wn * 32 + nt * 8 + 2 * rr;
                float bv0 = b2[c0], bv1 = b2[c0 + 1];
                float* d = acc[mt][nt];
                unsigned u0 = f2tf(fmaxf(d[0] + bv0, 0.f));
                unsigned u1 = f2tf(fmaxf(d[1] + bv1, 0.f));
                unsigned u2 = f2tf(fmaxf(d[2] + bv0, 0.f));
                unsigned u3 = f2tf(fmaxf(d[3] + bv1, 0.f));
                *(uint2*)(Hpu + r0 * ENC_HP_LD + c0)       = make_uint2(u0, u1);
                *(uint2*)(Hpu + (r0 + 8) * ENC_HP_LD + c0) = make_uint2(u2, u3);
            }
        }
    }
    __syncthreads();

    const int wm3 = wrp & 7, wn3 = wrp >> 3;
    unsigned* sWu = (unsigned*)buf;

    for (int nc = 0; nc < 8; ++nc) {
        {
            const float* src = (const float*)(g_W3tf + nc * 8192);
            for (int i = tid * 4; i < 8192; i += 2048) {
                int k = i >> 6, n = i & 63;
                cp16(bufaddr + (k * ENC_SW_LD + n) * 4, src + i);
            }
            CP_COMMIT();
            CP_WAIT0();
        }
        __syncthreads();

        float acc[4][4];
        #pragma unroll
        for (int nt = 0; nt < 4; ++nt)
            #pragma unroll
            for (int q = 0; q < 4; ++q) acc[nt][q] = 0.f;

        #pragma unroll 2
        for (int ks = 0; ks < 16; ++ks) {
            int k0 = ks * 8;
            unsigned af[4];
            {
                int r0 = wm3 * 16 + qp;
                af[0] = Hpu[r0 * ENC_HP_LD + k0 + rr];
                af[1] = Hpu[(r0 + 8) * ENC_HP_LD + k0 + rr];
                af[2] = Hpu[r0 * ENC_HP_LD + k0 + rr + 4];
                af[3] = Hpu[(r0 + 8) * ENC_HP_LD + k0 + rr + 4];
            }
            unsigned bf[4][2];
            #pragma unroll
            for (int nt = 0; nt < 4; ++nt) {
                int n = wn3 * 32 + nt * 8 + qp;
                bf[nt][0] = sWu[(k0 + rr) * ENC_SW_LD + n];
                bf[nt][1] = sWu[(k0 + 4 + rr) * ENC_SW_LD + n];
            }
            #pragma unroll
            for (int nt = 0; nt < 4; ++nt)
                mma_tf32(acc[nt], af, bf[nt]);
        }

        #pragma unroll
        for (int nt = 0; nt < 4; ++nt) {
            int n = wn3 * 32 + nt * 8 + 2 * rr;
            float bv0 = b3[nc * 64 + n];
            float bv1 = b3[nc * 64 + n + 1];
            float* d = acc[nt];
            float m0 = fmaxf(fmaxf(d[0] + bv0, d[2] + bv0), 0.f);
            float m1 = fmaxf(fmaxf(d[1] + bv1, d[3] + bv1), 0.f);
            #pragma unroll
            for (int s = 4; s < 32; s <<= 1) {
                m0 = fmaxf(m0, __shfl_xor_sync(0xffffffffu, m0, s));
                m1 = fmaxf(m1, __shfl_xor_sync(0xffffffffu, m1, s));
            }
            if (qp == 0) {
                sRed[wm3 * 64 + n]     = m0;
                sRed[wm3 * 64 + n + 1] = m1;
            }
        }
        __syncthreads();
        if (tid < 64) {
            float m = sRed[tid];
            #pragma unroll
            for (int w = 1; w < 8; ++w) m = fmaxf(m, sRed[w * 64 + tid]);
            atomicMax((int*)&g_feat[b * 512 + nc * 64 + tid], __float_as_int(m));
        }
    }
}

// ---------------------------------------------------------------------------
// Head MLP (identical to R13 passing version)
// ---------------------------------------------------------------------------
__global__ void __launch_bounds__(512) head_kernel(
    const float* __restrict__ w1, const float* __restrict__ b1,
    const float* __restrict__ w2, const float* __restrict__ b2,
    const float* __restrict__ w3, const float* __restrict__ b3)
{
    __shared__ float sh[512];
    __shared__ float pp[512];
    __shared__ float s1[256];
    __shared__ float s2[128];
    int b = blockIdx.x, tid = threadIdx.x;
    sh[tid] = g_feat[b * 512 + tid];
    __syncthreads();
    {
        int j = tid & 255, half = tid >> 8, k0 = half * 256;
        const float* wp = w1 + (size_t)k0 * 256 + j;
        float a0 = 0, a1 = 0, a2 = 0, a3 = 0;
        #pragma unroll 8
        for (int k = 0; k < 256; k += 4) {
            a0 += sh[k0 + k]     * wp[(size_t)k * 256];
            a1 += sh[k0 + k + 1] * wp[(size_t)(k + 1) * 256];
            a2 += sh[k0 + k + 2] * wp[(size_t)(k + 2) * 256];
            a3 += sh[k0 + k + 3] * wp[(size_t)(k + 3) * 256];
        }
        pp[tid] = (a0 + a1) + (a2 + a3);
    }
    __syncthreads();
    if (tid < 256) s1[tid] = fmaxf(b1[tid] + pp[tid] + pp[tid + 256], 0.f);
    __syncthreads();
    {
        int j = tid & 127, q = tid >> 7, k0 = q * 64;
        const float* wp = w2 + k0 * 128 + j;
        float a0 = 0, a1 = 0;
        #pragma unroll 8
        for (int k = 0; k < 64; k += 2) {
            a0 += s1[k0 + k]     * wp[k * 128];
            a1 += s1[k0 + k + 1] * wp[(k + 1) * 128];
        }
        pp[tid] = a0 + a1;
    }
    __syncthreads();
    if (tid < 128) s2[tid] = fmaxf(b2[tid] + pp[tid] + pp[tid + 128] + pp[tid + 256] + pp[tid + 384], 0.f);
    __syncthreads();
    {
        int j = tid & 255, half = tid >> 8, k0 = half * 64;
        const float* wp = w3 + k0 * 256 + j;
        float a0 = 0, a1 = 0;
        #pragma unroll 8
        for (int k = 0; k < 64; k += 2) {
            a0 += s2[k0 + k]     * wp[k * 256];
            a1 += s2[k0 + k + 1] * wp[(k + 1) * 256];
        }
        pp[tid] = a0 + a1;
    }
    __syncthreads();
    if (tid < 256) g_gruh[b * HID + tid] = b3[tid] + pp[tid] + pp[tid + 256];
}

// ---------------------------------------------------------------------------
// GRU rollout v10: R13 pair topology, gather phase ELIMINATED —
// gates read partner gh/x directly from the L2 payload (coalesced __ldcg).
// 128 blocks x 768 threads.
// ---------------------------------------------------------------------------
#define GRU_SMEM_FLOATS 44328

__global__ void __launch_bounds__(768) gru_kernel(
    const float* __restrict__ Wih, const float* __restrict__ bih, const float* __restrict__ bhh,
    const float* __restrict__ ow1, const float* __restrict__ ob1,
    const float* __restrict__ ow2, const float* __restrict__ ob2,
    const float* __restrict__ ow3, const float* __restrict__ ob3,
    const int* __restrict__ horizon_p, float* __restrict__ out, int out_size)
{
    extern __shared__ float sm[];
    float* s_Wih  = sm;                   // 4608
    float* s_bih  = s_Wih + 4608;         // 768
    float* s_bhh  = s_bih + 768;          // 768
    float* s_w1   = s_bhh + 768;          // 16384
    float* s_w2   = s_w1 + 16384;         // 4096
    float* s_w3   = s_w2 + 4096;          // 384
    float* s_b1   = s_w3 + 384;           // 64
    float* s_b2   = s_b1 + 64;            // 64
    float* s_b3   = s_b2 + 64;            // 8
    float* s_h    = s_b3 + 8;             // 1024
    float* s_x    = s_h + 1024;           // 32
    float* s_gh   = s_x + 32;             // 3072 (own half written only)
    float* s_part = s_gh + 3072;          // 12288 (8 slices x 96 jg x 16)
    float* s_p1   = s_part + 12288;       // 512
    float* s_o1   = s_p1 + 512;           // 128
    float* s_o2   = s_o1 + 128;           // 128

    const int tid     = threadIdx.x;
    const int bid     = blockIdx.x;
    const int pairid  = bid >> 1;
    const int half    = bid & 1;
    const int partner = bid ^ 1;
    const int b0      = pairid * 4;

    for (int i = tid; i < 4608;  i += 768) s_Wih[i] = Wih[i];
    for (int i = tid; i < 768;   i += 768) { s_bih[i] = bih[i]; s_bhh[i] = bhh[i]; }
    for (int i = tid; i < 16384; i += 768) s_w1[i] = ow1[i];
    for (int i = tid; i < 4096;  i += 768) s_w2[i] = ow2[i];
    if (tid < 384) s_w3[tid] = ow3[tid];
    if (tid < 64) { s_b1[tid] = ob1[tid]; s_b2[tid] = ob2[tid]; }
    if (tid < 6)  s_b3[tid] = ob3[tid];
    for (int i = tid; i < 1024; i += 768) {
        int r = i >> 8, k = i & 255;
        s_h[i] = g_gruh[(b0 + r) * HID + k];
    }
    if (tid < 32) s_x[tid] = 0.f;
    __syncthreads();

    int T = 50;
    if (horizon_p) {
        int v = *horizon_p;
        if (v > 0 && v <= 1000000) T = v;
        else {
            float fv = __int_as_float(v);
            if (fv > 0.f && fv <= 1000000.f) T = (int)fv;
        }
    }
    const int off2 = out_size >> 1;

    const int jg   = tid % 96;
    const int ks   = tid / 96;
    const int k0   = ks * 32;
    const int jcol = half * 384 + jg * 4;
    const float* Wcol = g_WhhT + jcol;

    const int jgR = tid >> 3;
    const int rR  = (tid >> 1) & 3;
    const int cpR = tid & 1;

    for (int t = 0; t < T; ++t) {
        const int par = t & 1;
        float* pay_out = &g_pay[par][bid][0];
        const float* pay_in = &g_pay[par][partner][0];

        // ---- gh-half GEMM: 4 rows x 4 cols per thread over 32 k ----
        float acc[4][4];
        #pragma unroll
        for (int r = 0; r < 4; ++r)
            #pragma unroll
            for (int c = 0; c < 4; ++c) acc[r][c] = 0.f;

        #pragma unroll 2
        for (int kk = 0; kk < 32; kk += 4) {
            float4 h0 = *(float4*)&s_h[0 * 256 + k0 + kk];
            float4 h1 = *(float4*)&s_h[1 * 256 + k0 + kk];
            float4 h2 = *(float4*)&s_h[2 * 256 + k0 + kk];
            float4 h3 = *(float4*)&s_h[3 * 256 + k0 + kk];
            const float* wb = Wcol + (size_t)(k0 + kk) * 768;
            #pragma unroll
            for (int q = 0; q < 4; ++q) {
                float4 w = *(const float4*)(wb + (size_t)q * 768);
                float a0 = (q == 0) ? h0.x : (q == 1) ? h0.y : (q == 2) ? h0.z : h0.w;
                float a1 = (q == 0) ? h1.x : (q == 1) ? h1.y : (q == 2) ? h1.z : h1.w;
                float a2 = (q == 0) ? h2.x : (q == 1) ? h2.y : (q == 2) ? h2.z : h2.w;
                float a3 = (q == 0) ? h3.x : (q == 1) ? h3.y : (q == 2) ? h3.z : h3.w;
                acc[0][0] += a0*w.x; acc[0][1] += a0*w.y; acc[0][2] += a0*w.z; acc[0][3] += a0*w.w;
                acc[1][0] += a1*w.x; acc[1][1] += a1*w.y; acc[1][2] += a1*w.z; acc[1][3] += a1*w.w;
                acc[2][0] += a2*w.x; acc[2][1] += a2*w.y; acc[2][2] += a2*w.z; acc[2][3] += a2*w.w;
                acc[3][0] += a3*w.x; acc[3][1] += a3*w.y; acc[3][2] += a3*w.z; acc[3][3] += a3*w.w;
            }
        }

        // ---- store partials, fully parallel reduce over 8 k-slices ----
        {
            float* p = &s_part[(ks * 96 + jg) * 16];
            #pragma unroll
            for (int r = 0; r < 4; ++r)
                *(float4*)(p + r * 4) = make_float4(acc[r][0], acc[r][1], acc[r][2], acc[r][3]);
        }
        __syncthreads();
        {
            float sx = 0.f, sy = 0.f;
            #pragma unroll
            for (int s8 = 0; s8 < 8; ++s8) {
                float2 v = *(float2*)&s_part[(s8 * 96 + jgR) * 16 + rR * 4 + cpR * 2];
                sx += v.x; sy += v.y;
            }
            float2 res = make_float2(sx, sy);
            int jloc = jgR * 4 + cpR * 2;
            *(float2*)&s_gh[rR * 768 + half * 384 + jloc] = res;
            *(float2*)&pay_out[rR * 384 + jloc] = res;
        }
        if (tid < 12) {
            int rl = tid / 6, a = tid % 6;
            pay_out[1536 + tid] = s_x[(half * 2 + rl) * 8 + a];
        }
        __syncthreads();
        if (tid == 0) {
            asm volatile("fence.acq_rel.gpu;" ::: "memory");
            atomicExch(&g_flag[bid], t + 1);
            int v;
            do {
                asm volatile("ld.acquire.gpu.global.b32 %0, [%1];"
                             : "=r"(v) : "l"(&g_flag[partner]) : "memory");
            } while (v < t + 1);
        }
        __syncthreads();

        // ---- gates + h update: partner gh/x read DIRECTLY from payload ----
        #pragma unroll
        for (int it = 0; it < 2; ++it) {
            int item = tid + it * 768;
            if (item < 1024) {
                int r = item >> 8, kk = item & 255;
                bool own_r = ((r >> 1) == half);
                float x0, x1, x2, x3, x4, x5;
                if (own_r) {
                    x0 = s_x[r*8+0]; x1 = s_x[r*8+1]; x2 = s_x[r*8+2];
                    x3 = s_x[r*8+3]; x4 = s_x[r*8+4]; x5 = s_x[r*8+5];
                } else {
                    int rl = r & 1;
                    x0 = __ldcg(&pay_in[1536 + rl*6 + 0]);
                    x1 = __ldcg(&pay_in[1536 + rl*6 + 1]);
                    x2 = __ldcg(&pay_in[1536 + rl*6 + 2]);
                    x3 = __ldcg(&pay_in[1536 + rl*6 + 3]);
                    x4 = __ldcg(&pay_in[1536 + rl*6 + 4]);
                    x5 = __ldcg(&pay_in[1536 + rl*6 + 5]);
                }
                const float* wr = s_Wih + kk * 6;
                const float* wz = s_Wih + (256 + kk) * 6;
                const float* wn = s_Wih + (512 + kk) * 6;
                float gir = s_bih[kk]       + x0*wr[0]+x1*wr[1]+x2*wr[2]+x3*wr[3]+x4*wr[4]+x5*wr[5];
                float giz = s_bih[256 + kk] + x0*wz[0]+x1*wz[1]+x2*wz[2]+x3*wz[3]+x4*wz[4]+x5*wz[5];
                float gin = s_bih[512 + kk] + x0*wn[0]+x1*wn[1]+x2*wn[2]+x3*wn[3]+x4*wn[4]+x5*wn[5];
                // gh columns: r-gate = kk (half0), z-gate = 256+kk (kk<128 ? half0 : half1),
                // n-gate = 512+kk (half1). Own half -> smem; other -> payload.
                int cz = 256 + kk;
                float ghr_v = (half == 0) ? s_gh[r*768 + kk]
                                          : __ldcg(&pay_in[r*384 + kk]);
                float ghz_v;
                if (kk < 128)
                    ghz_v = (half == 0) ? s_gh[r*768 + cz] : __ldcg(&pay_in[r*384 + cz]);
                else
                    ghz_v = (half == 1) ? s_gh[r*768 + cz] : __ldcg(&pay_in[r*384 + cz - 384]);
                float ghn_v = (half == 1) ? s_gh[r*768 + 512 + kk]
                                          : __ldcg(&pay_in[r*384 + 128 + kk]);
                float rr2 = sigf(gir + ghr_v + s_bhh[kk]);
                float zz = sigf(giz + ghz_v + s_bhh[256 + kk]);
                float nn = tanhfast(gin + rr2 * (ghn_v + s_bhh[512 + kk]));
                s_h[r*256 + kk] = (1.f - zz) * nn + zz * s_h[r*256 + kk];
            }
        }
        __syncthreads();

        // ---- out MLP for own 2 rows: 256 -> 64 -> 64 -> 6 (4-way k-split) ----
        if (tid < 512) {
            int rl = tid >> 8, kq = (tid >> 6) & 3, j = tid & 63;
            const float* hb = s_h + (half * 2 + rl) * 256 + kq * 64;
            const float* wp = s_w1 + (kq * 64) * 64 + j;
            float a0 = 0, a1 = 0;
            #pragma unroll 8
            for (int k = 0; k < 64; k += 2) {
                a0 += hb[k]     * wp[k * 64];
                a1 += hb[k + 1] * wp[(k + 1) * 64];
            }
            s_p1[(rl * 4 + kq) * 64 + j] = a0 + a1;
        }
        __syncthreads();
        if (tid < 128) {
            int rl = tid >> 6, j = tid & 63;
            const float* p = s_p1 + rl * 256 + j;
            s_o1[tid] = fmaxf(s_b1[j] + (p[0] + p[64]) + (p[128] + p[192]), 0.f);
        }
        __syncthreads();
        if (tid < 128) {
            int rl = tid >> 6, j = tid & 63;
            float a0 = 0, a1 = 0;
            #pragma unroll 8
            for (int k = 0; k < 64; k += 2) {
                a0 += s_o1[rl*64 + k]     * s_w2[k * 64 + j];
                a1 += s_o1[rl*64 + k + 1] * s_w2[(k + 1) * 64 + j];
            }
            s_o2[tid] = fmaxf(s_b2[j] + a0 + a1, 0.f);
        }
        __syncthreads();
        if (tid < 12) {
            int rl = tid / 6, a = tid % 6;
            float d0 = 0, d1 = 0;
            #pragma unroll 8
            for (int k = 0; k < 64; k += 2) {
                d0 += s_o2[rl*64 + k]     * s_w3[k * 6 + a];
                d1 += s_o2[rl*64 + k + 1] * s_w3[(k + 1) * 6 + a];
            }
            float d = s_b3[a] + d0 + d1;
            int rloc = half * 2 + rl;
            float xn = s_x[rloc * 8 + a] + d;
            s_x[rloc * 8 + a] = xn;
            int b = b0 + rloc;
            size_t o = ((size_t)b * T + t) * 6 + a;
            out[o] = d;
            out[off2 + o] = xn;
        }
        __syncthreads();
    }
}

// ---------------------------------------------------------------------------
// launch
// ---------------------------------------------------------------------------
extern "C" void kernel_launch(void* const* d_in, const int* in_sizes, int n_in,
                              void* d_out, int out_size)
{
    int hpos = -1;
    for (int i = 0; i < n_in; ++i) if (in_sizes[i] == 1) hpos = i;

    const float* ins[23];
    int j = 0;
    for (int i = 0; i < n_in && j < 23; ++i) {
        if (i == hpos) continue;
        ins[j++] = (const float*)d_in[i];
    }
    const int* hp = (hpos >= 0) ? (const int*)d_in[hpos] : nullptr;

    // ins: 0 data | 1 enc_w1 2 enc_b1 3 enc_w2 4 enc_b2 5 enc_w3 6 enc_b3
    //      7 mlp_w1 8 mlp_b1 9 mlp_w2 10 mlp_b2 11 mlp_w3 12 mlp_b3
    //      13 W_ih 14 W_hh 15 b_ih 16 b_hh
    //      17 out_w1 18 out_b1 19 out_w2 20 out_b2 21 out_w3 22 out_b3

    const int enc_smem = ENC_SMEM_FLOATS * 4;
    const int gru_smem = GRU_SMEM_FLOATS * 4;
    cudaFuncSetAttribute(enc_kernel, cudaFuncAttributeMaxDynamicSharedMemorySize, enc_smem);
    cudaFuncSetAttribute(gru_kernel, cudaFuncAttributeMaxDynamicSharedMemorySize, gru_smem);

    prep_kernel<<<1569, 256>>>(ins[14], ins[5], ins[3]);
    enc_kernel<<<dim3(8, 256), 512, enc_smem>>>(ins[0], ins[1], ins[2], ins[4], ins[6]);
    head_kernel<<<256, 512>>>(ins[7], ins[8], ins[9], ins[10], ins[11], ins[12]);
    gru_kernel<<<GRU_BLOCKS, 768, gru_smem>>>(ins[13], ins[15], ins[16],
                                              ins[17], ins[18], ins[19], ins[20], ins[21], ins[22],
                                              hp, (float*)d_out, out_size);
}

// round 16
// speedup vs baseline: 1.1479x; 1.0422x over previous
#include <cuda_runtime.h>
#include <cuda_bf16.h>
#include <cstdint>
#include <cstddef>

// ---------------------------------------------------------------------------
// Problem constants
// ---------------------------------------------------------------------------
#define BATCH   256
#define NPTS    1024
#define HID     256
#define ACT     6
#define GRU_BLOCKS 128

// device scratch
__device__ float g_feat[BATCH * 512];
__device__ float g_gruh[BATCH * HID];
__device__ float g_WhhT[HID * 768];
__device__ unsigned g_W3tf[8 * 128 * 64];    // tf32 image, [chunk8][k][n64]
__device__ unsigned g_W2tf[64 * 128];        // tf32 image of W2 [k][j]
// GRU pair-exchange payload: [parity][block][4*384 gh + 12 x] + flags
__device__ float g_pay[2][GRU_BLOCKS][1552];
__device__ int   g_flag[GRU_BLOCKS];

// ---------------------------------------------------------------------------
// helpers
// ---------------------------------------------------------------------------
__device__ __forceinline__ unsigned f2tf(float x) {
    unsigned u; asm("cvt.rna.tf32.f32 %0, %1;" : "=r"(u) : "f"(x)); return u;
}

__device__ __forceinline__ void mma_tf32(float* d, const unsigned* a, const unsigned* b) {
    asm volatile(
        "mma.sync.aligned.m16n8k8.row.col.f32.tf32.tf32.f32 "
        "{%0,%1,%2,%3}, {%4,%5,%6,%7}, {%8,%9}, {%0,%1,%2,%3};\n"
        : "+f"(d[0]), "+f"(d[1]), "+f"(d[2]), "+f"(d[3])
        : "r"(a[0]), "r"(a[1]), "r"(a[2]), "r"(a[3]), "r"(b[0]), "r"(b[1]));
}

__device__ __forceinline__ void cp16(uint32_t dst_smem, const void* src) {
    asm volatile("cp.async.cg.shared.global [%0], [%1], 16;" :: "r"(dst_smem), "l"(src));
}
#define CP_COMMIT() asm volatile("cp.async.commit_group;" ::: "memory")
#define CP_WAIT0()  asm volatile("cp.async.wait_group 0;" ::: "memory")

__device__ __forceinline__ float sigf(float x) {
    return __fdividef(1.f, 1.f + __expf(-x));
}
__device__ __forceinline__ float tanhfast(float x) {
    return __fdividef(2.f, 1.f + __expf(-2.f * x)) - 1.f;
}

// ---------------------------------------------------------------------------
// fused prep kernel: zero_feat | Whh transpose | W3 tf32 | W2 tf32 | flags
// ---------------------------------------------------------------------------
__global__ void prep_kernel(const float* __restrict__ Whh,
                            const float* __restrict__ w3,
                            const float* __restrict__ w2) {
    int idx = blockIdx.x * 256 + threadIdx.x;
    if (idx < 131072) { g_feat[idx] = 0.f; return; }
    idx -= 131072;
    if (idx < 196608) {
        int k = idx / 768, j = idx - k * 768;
        g_WhhT[idx] = Whh[j * 256 + k];
        return;
    }
    idx -= 196608;
    if (idx < 65536) {
        int c = idx >> 13;
        int r = idx & 8191;
        int k = r >> 6, n = r & 63;
        g_W3tf[idx] = f2tf(w3[(size_t)k * 512 + c * 64 + n]);
        return;
    }
    idx -= 65536;
    if (idx < 8192) { g_W2tf[idx] = f2tf(w2[idx]); return; }
    idx -= 8192;
    if (idx < GRU_BLOCKS) g_flag[idx] = 0;
}

// ---------------------------------------------------------------------------
// Fused PointNet encoder: 3->64 (fp32) -> 128 (tf32 mma) -> 512 (tf32 mma)
// R13 structure (2 blocks/SM) + cp.async of the NEXT chunk overlapped with
// the current chunk's epilogue (and chunk 0 with layer-2's epilogue).
// ---------------------------------------------------------------------------
#define ENC_HP_LD 132
#define ENC_B2_LD 136
#define ENC_SW_LD 72
#define ENC_A2_LD 68
#define ENC_SMEM_FLOATS (16896 + 9216 + 512)

__global__ void __launch_bounds__(512, 2) enc_kernel(
    const float* __restrict__ data,
    const float* __restrict__ w1, const float* __restrict__ b1,
    const float* __restrict__ b2, const float* __restrict__ b3)
{
    extern __shared__ float sm[];
    float* Hp   = sm;
    float* buf  = sm + 16896;
    float* sRed = sm + 16896 + 9216;
    __shared__ float sPts[128 * 3];

    const int tid   = threadIdx.x;
    const int b     = blockIdx.y;
    const int chunk = blockIdx.x;

    unsigned* A2 = (unsigned*)sm;
    unsigned* B2 = (unsigned*)buf;
    uint32_t bufaddr = (uint32_t)__cvta_generic_to_shared(buf);

    const float* dptr = data + (size_t)(b * NPTS + chunk * 128) * 3;
    if (tid < 384) sPts[tid] = dptr[tid];
    for (int idx = tid; idx < 8192; idx += 512) {
        int k = idx >> 7, j = idx & 127;
        B2[k * ENC_B2_LD + j] = g_W2tf[idx];
    }
    __syncthreads();

    #pragma unroll
    for (int it = 0; it < 16; ++it) {
        int idx = tid + it * 512;
        int k = idx >> 7, i = idx & 127;
        float v = b1[k] + sPts[i*3] * w1[k] + sPts[i*3+1] * w1[64 + k] + sPts[i*3+2] * w1[128 + k];
        A2[i * ENC_A2_LD + k] = f2tf(fmaxf(v, 0.f));
    }
    __syncthreads();

    const int lane = tid & 31, wrp = tid >> 5;
    const int qp = lane >> 2, rr = lane & 3;
    unsigned* Hpu = (unsigned*)Hp;

    // ---- layer 2 via tf32 mma: M=128, N=128, K=64 (warp grid 4x4) ----
    {
        const int wm = wrp & 3, wn = wrp >> 2;
        float acc[2][4][4];
        #pragma unroll
        for (int mt = 0; mt < 2; ++mt)
            #pragma unroll
            for (int nt = 0; nt < 4; ++nt)
                #pragma unroll
                for (int q = 0; q < 4; ++q) acc[mt][nt][q] = 0.f;

        #pragma unroll 2
        for (int ks = 0; ks < 8; ++ks) {
            int k0 = ks * 8;
            unsigned af[2][4];
            #pragma unroll
            for (int mt = 0; mt < 2; ++mt) {
                int r0 = wm * 32 + mt * 16 + qp;
                af[mt][0] = A2[r0 * ENC_A2_LD + k0 + rr];
                af[mt][1] = A2[(r0 + 8) * ENC_A2_LD + k0 + rr];
                af[mt][2] = A2[r0 * ENC_A2_LD + k0 + rr + 4];
                af[mt][3] = A2[(r0 + 8) * ENC_A2_LD + k0 + rr + 4];
            }
            unsigned bf[4][2];
            #pragma unroll
            for (int nt = 0; nt < 4; ++nt) {
                int n = wn * 32 + nt * 8 + qp;
                bf[nt][0] = B2[(k0 + rr) * ENC_B2_LD + n];
                bf[nt][1] = B2[(k0 + 4 + rr) * ENC_B2_LD + n];
            }
            #pragma unroll
            for (int mt = 0; mt < 2; ++mt)
                #pragma unroll
                for (int nt = 0; nt < 4; ++nt)
                    mma_tf32(acc[mt][nt], af[mt], bf[nt]);
        }
        __syncthreads();   // A2 reads AND B2(buf) reads complete

        // issue chunk-0 stage into buf, overlapped with layer-2 epilogue
        {
            const float* src = (const float*)(g_W3tf);
            for (int i = tid * 4; i < 8192; i += 2048) {
                int k = i >> 6, n = i & 63;
                cp16(bufaddr + (k * ENC_SW_LD + n) * 4, src + i);
            }
            CP_COMMIT();
        }

        #pragma unroll
        for (int mt = 0; mt < 2; ++mt) {
            int r0 = wm * 32 + mt * 16 + qp;
            #pragma unroll
            for (int nt = 0; nt < 4; ++nt) {
                int c0 = wn * 32 + nt * 8 + 2 * rr;
                float bv0 = b2[c0], bv1 = b2[c0 + 1];
                float* d = acc[mt][nt];
                unsigned u0 = f2tf(fmaxf(d[0] + bv0, 0.f));
                unsigned u1 = f2tf(fmaxf(d[1] + bv1, 0.f));
                unsigned u2 = f2tf(fmaxf(d[2] + bv0, 0.f));
                unsigned u3 = f2tf(fmaxf(d[3] + bv1, 0.f));
                *(uint2*)(Hpu + r0 * ENC_HP_LD + c0)       = make_uint2(u0, u1);
                *(uint2*)(Hpu + (r0 + 8) * ENC_HP_LD + c0) = make_uint2(u2, u3);
            }
        }
    }

    // ---- layer 3: 8 N-chunks of 64 cols, warp grid 8x2, pipelined stage ----
    const int wm3 = wrp & 7, wn3 = wrp >> 3;
    unsigned* sWu = (unsigned*)buf;

    for (int nc = 0; nc < 8; ++nc) {
        CP_WAIT0();
        __syncthreads();   // chunk nc landed; Hp writes (nc==0) / sRed reads visible

        float acc[4][4];
        #pragma unroll
        for (int nt = 0; nt < 4; ++nt)
            #pragma unroll
            for (int q = 0; q < 4; ++q) acc[nt][q] = 0.f;

        #pragma unroll 2
        for (int ks = 0; ks < 16; ++ks) {
            int k0 = ks * 8;
            unsigned af[4];
            {
                int r0 = wm3 * 16 + qp;
                af[0] = Hpu[r0 * ENC_HP_LD + k0 + rr];
                af[1] = Hpu[(r0 + 8) * ENC_HP_LD + k0 + rr];
                af[2] = Hpu[r0 * ENC_HP_LD + k0 + rr + 4];
                af[3] = Hpu[(r0 + 8) * ENC_HP_LD + k0 + rr + 4];
            }
            unsigned bf[4][2];
            #pragma unroll
            for (int nt = 0; nt < 4; ++nt) {
                int n = wn3 * 32 + nt * 8 + qp;
                bf[nt][0] = sWu[(k0 + rr) * ENC_SW_LD + n];
                bf[nt][1] = sWu[(k0 + 4 + rr) * ENC_SW_LD + n];
            }
            #pragma unroll
            for (int nt = 0; nt < 4; ++nt)
                mma_tf32(acc[nt], af, bf[nt]);
        }
        __syncthreads();   // all warps done reading buf

        // stage chunk nc+1 (in flight during epilogue + atomics)
        if (nc < 7) {
            const float* src = (const float*)(g_W3tf + (nc + 1) * 8192);
            for (int i = tid * 4; i < 8192; i += 2048) {
                int k = i >> 6, n = i & 63;
                cp16(bufaddr + (k * ENC_SW_LD + n) * 4, src + i);
            }
            CP_COMMIT();
        }

        #pragma unroll
        for (int nt = 0; nt < 4; ++nt) {
            int n = wn3 * 32 + nt * 8 + 2 * rr;
            float bv0 = b3[nc * 64 + n];
            float bv1 = b3[nc * 64 + n + 1];
            float* d = acc[nt];
            float m0 = fmaxf(fmaxf(d[0] + bv0, d[2] + bv0), 0.f);
            float m1 = fmaxf(fmaxf(d[1] + bv1, d[3] + bv1), 0.f);
            #pragma unroll
            for (int s = 4; s < 32; s <<= 1) {
                m0 = fmaxf(m0, __shfl_xor_sync(0xffffffffu, m0, s));
                m1 = fmaxf(m1, __shfl_xor_sync(0xffffffffu, m1, s));
            }
            if (qp == 0) {
                sRed[wm3 * 64 + n]     = m0;
                sRed[wm3 * 64 + n + 1] = m1;
            }
        }
        __syncthreads();   // sRed ready
        if (tid < 64) {
            float m = sRed[tid];
            #pragma unroll
            for (int w = 1; w < 8; ++w) m = fmaxf(m, sRed[w * 64 + tid]);
            atomicMax((int*)&g_feat[b * 512 + nc * 64 + tid], __float_as_int(m));
        }
        // the CP_WAIT0 + sync at loop top orders sRed reads before next writes
    }
}

// ---------------------------------------------------------------------------
// Head MLP (identical to R13 passing version)
// ---------------------------------------------------------------------------
__global__ void __launch_bounds__(512) head_kernel(
    const float* __restrict__ w1, const float* __restrict__ b1,
    const float* __restrict__ w2, const float* __restrict__ b2,
    const float* __restrict__ w3, const float* __restrict__ b3)
{
    __shared__ float sh[512];
    __shared__ float pp[512];
    __shared__ float s1[256];
    __shared__ float s2[128];
    int b = blockIdx.x, tid = threadIdx.x;
    sh[tid] = g_feat[b * 512 + tid];
    __syncthreads();
    {
        int j = tid & 255, half = tid >> 8, k0 = half * 256;
        const float* wp = w1 + (size_t)k0 * 256 + j;
        float a0 = 0, a1 = 0, a2 = 0, a3 = 0;
        #pragma unroll 8
        for (int k = 0; k < 256; k += 4) {
            a0 += sh[k0 + k]     * wp[(size_t)k * 256];
            a1 += sh[k0 + k + 1] * wp[(size_t)(k + 1) * 256];
            a2 += sh[k0 + k + 2] * wp[(size_t)(k + 2) * 256];
            a3 += sh[k0 + k + 3] * wp[(size_t)(k + 3) * 256];
        }
        pp[tid] = (a0 + a1) + (a2 + a3);
    }
    __syncthreads();
    if (tid < 256) s1[tid] = fmaxf(b1[tid] + pp[tid] + pp[tid + 256], 0.f);
    __syncthreads();
    {
        int j = tid & 127, q = tid >> 7, k0 = q * 64;
        const float* wp = w2 + k0 * 128 + j;
        float a0 = 0, a1 = 0;
        #pragma unroll 8
        for (int k = 0; k < 64; k += 2) {
            a0 += s1[k0 + k]     * wp[k * 128];
            a1 += s1[k0 + k + 1] * wp[(k + 1) * 128];
        }
        pp[tid] = a0 + a1;
    }
    __syncthreads();
    if (tid < 128) s2[tid] = fmaxf(b2[tid] + pp[tid] + pp[tid + 128] + pp[tid + 256] + pp[tid + 384], 0.f);
    __syncthreads();
    {
        int j = tid & 255, half = tid >> 8, k0 = half * 64;
        const float* wp = w3 + k0 * 256 + j;
        float a0 = 0, a1 = 0;
        #pragma unroll 8
        for (int k = 0; k < 64; k += 2) {
            a0 += s2[k0 + k]     * wp[k * 256];
            a1 += s2[k0 + k + 1] * wp[(k + 1) * 256];
        }
        pp[tid] = a0 + a1;
    }
    __syncthreads();
    if (tid < 256) g_gruh[b * HID + tid] = b3[tid] + pp[tid] + pp[tid + 256];
}

// ---------------------------------------------------------------------------
// GRU rollout (R13 passing version, verbatim structure): 128 blocks = 64
// pairs, 768 threads, parallel slice reduce, acq/rel flag exchange, gather.
// ---------------------------------------------------------------------------
#define GRU_SMEM_FLOATS 44328

__global__ void __launch_bounds__(768) gru_kernel(
    const float* __restrict__ Wih, const float* __restrict__ bih, const float* __restrict__ bhh,
    const float* __restrict__ ow1, const float* __restrict__ ob1,
    const float* __restrict__ ow2, const float* __restrict__ ob2,
    const float* __restrict__ ow3, const float* __restrict__ ob3,
    const int* __restrict__ horizon_p, float* __restrict__ out, int out_size)
{
    extern __shared__ float sm[];
    float* s_Wih  = sm;                   // 4608
    float* s_bih  = s_Wih + 4608;         // 768
    float* s_bhh  = s_bih + 768;          // 768
    float* s_w1   = s_bhh + 768;          // 16384
    float* s_w2   = s_w1 + 16384;         // 4096
    float* s_w3   = s_w2 + 4096;          // 384
    float* s_b1   = s_w3 + 384;           // 64
    float* s_b2   = s_b1 + 64;            // 64
    float* s_b3   = s_b2 + 64;            // 8
    float* s_h    = s_b3 + 8;             // 1024
    float* s_x    = s_h + 1024;           // 32
    float* s_gh   = s_x + 32;             // 3072
    float* s_part = s_gh + 3072;          // 12288 (8 slices x 96 jg x 16)
    float* s_p1   = s_part + 12288;       // 512
    float* s_o1   = s_p1 + 512;           // 128
    float* s_o2   = s_o1 + 128;           // 128

    const int tid     = threadIdx.x;
    const int bid     = blockIdx.x;
    const int pairid  = bid >> 1;
    const int half    = bid & 1;
    const int partner = bid ^ 1;
    const int b0      = pairid * 4;

    for (int i = tid; i < 4608;  i += 768) s_Wih[i] = Wih[i];
    for (int i = tid; i < 768;   i += 768) { s_bih[i] = bih[i]; s_bhh[i] = bhh[i]; }
    for (int i = tid; i < 16384; i += 768) s_w1[i] = ow1[i];
    for (int i = tid; i < 4096;  i += 768) s_w2[i] = ow2[i];
    if (tid < 384) s_w3[tid] = ow3[tid];
    if (tid < 64) { s_b1[tid] = ob1[tid]; s_b2[tid] = ob2[tid]; }
    if (tid < 6)  s_b3[tid] = ob3[tid];
    for (int i = tid; i < 1024; i += 768) {
        int r = i >> 8, k = i & 255;
        s_h[i] = g_gruh[(b0 + r) * HID + k];
    }
    if (tid < 32) s_x[tid] = 0.f;
    __syncthreads();

    int T = 50;
    if (horizon_p) {
        int v = *horizon_p;
        if (v > 0 && v <= 1000000) T = v;
        else {
            float fv = __int_as_float(v);
            if (fv > 0.f && fv <= 1000000.f) T = (int)fv;
        }
    }
    const int off2 = out_size >> 1;

    const int jg   = tid % 96;
    const int ks   = tid / 96;
    const int k0   = ks * 32;
    const int jcol = half * 384 + jg * 4;
    const float* Wcol = g_WhhT + jcol;

    const int jgR = tid >> 3;
    const int rR  = (tid >> 1) & 3;
    const int cpR = tid & 1;

    for (int t = 0; t < T; ++t) {
        const int par = t & 1;
        float* pay_out = &g_pay[par][bid][0];
        const float* pay_in = &g_pay[par][partner][0];

        // ---- gh-half GEMM: 4 rows x 4 cols per thread over 32 k ----
        float acc[4][4];
        #pragma unroll
        for (int r = 0; r < 4; ++r)
            #pragma unroll
            for (int c = 0; c < 4; ++c) acc[r][c] = 0.f;

        #pragma unroll 2
        for (int kk = 0; kk < 32; kk += 4) {
            float4 h0 = *(float4*)&s_h[0 * 256 + k0 + kk];
            float4 h1 = *(float4*)&s_h[1 * 256 + k0 + kk];
            float4 h2 = *(float4*)&s_h[2 * 256 + k0 + kk];
            float4 h3 = *(float4*)&s_h[3 * 256 + k0 + kk];
            const float* wb = Wcol + (size_t)(k0 + kk) * 768;
            #pragma unroll
            for (int q = 0; q < 4; ++q) {
                float4 w = *(const float4*)(wb + (size_t)q * 768);
                float a0 = (q == 0) ? h0.x : (q == 1) ? h0.y : (q == 2) ? h0.z : h0.w;
                float a1 = (q == 0) ? h1.x : (q == 1) ? h1.y : (q == 2) ? h1.z : h1.w;
                float a2 = (q == 0) ? h2.x : (q == 1) ? h2.y : (q == 2) ? h2.z : h2.w;
                float a3 = (q == 0) ? h3.x : (q == 1) ? h3.y : (q == 2) ? h3.z : h3.w;
                acc[0][0] += a0*w.x; acc[0][1] += a0*w.y; acc[0][2] += a0*w.z; acc[0][3] += a0*w.w;
                acc[1][0] += a1*w.x; acc[1][1] += a1*w.y; acc[1][2] += a1*w.z; acc[1][3] += a1*w.w;
                acc[2][0] += a2*w.x; acc[2][1] += a2*w.y; acc[2][2] += a2*w.z; acc[2][3] += a2*w.w;
                acc[3][0] += a3*w.x; acc[3][1] += a3*w.y; acc[3][2] += a3*w.z; acc[3][3] += a3*w.w;
            }
        }

        // ---- store partials, fully parallel reduce over 8 k-slices ----
        {
            float* p = &s_part[(ks * 96 + jg) * 16];
            #pragma unroll
            for (int r = 0; r < 4; ++r)
                *(float4*)(p + r * 4) = make_float4(acc[r][0], acc[r][1], acc[r][2], acc[r][3]);
        }
        __syncthreads();
        {
            float sx = 0.f, sy = 0.f;
            #pragma unroll
            for (int s8 = 0; s8 < 8; ++s8) {
                float2 v = *(float2*)&s_part[(s8 * 96 + jgR) * 16 + rR * 4 + cpR * 2];
                sx += v.x; sy += v.y;
            }
            float2 res = make_float2(sx, sy);
            int jloc = jgR * 4 + cpR * 2;
            *(float2*)&s_gh[rR * 768 + half * 384 + jloc] = res;
            *(float2*)&pay_out[rR * 384 + jloc] = res;
        }
        if (tid < 12) {
            int rl = tid / 6, a = tid % 6;
            pay_out[1536 + tid] = s_x[(half * 2 + rl) * 8 + a];
        }
        __syncthreads();
        if (tid == 0) {
            asm volatile("fence.acq_rel.gpu;" ::: "memory");
            atomicExch(&g_flag[bid], t + 1);
            int v;
            do {
                asm volatile("ld.acquire.gpu.global.b32 %0, [%1];"
                             : "=r"(v) : "l"(&g_flag[partner]) : "memory");
            } while (v < t + 1);
        }
        __syncthreads();

        // ---- gather partner half into s_gh + partner x ----
        if (tid < 384) {
            int rr = tid / 96, off = (tid % 96) * 4;
            float4 v = __ldcg((const float4*)&pay_in[rr * 384 + off]);
            *(float4*)&s_gh[rr * 768 + (half ^ 1) * 384 + off] = v;
        }
        if (tid < 12) {
            int rl = tid / 6, a = tid % 6;
            s_x[((half ^ 1) * 2 + rl) * 8 + a] = __ldcg(&pay_in[1536 + tid]);
        }
        __syncthreads();

        // ---- gates + h update (all 4 rows) ----
        #pragma unroll
        for (int it = 0; it < 2; ++it) {
            int item = tid + it * 768;
            if (item < 1024) {
                int r = item >> 8, kk = item & 255;
                float x0 = s_x[r*8+0], x1 = s_x[r*8+1], x2 = s_x[r*8+2];
                float x3 = s_x[r*8+3], x4 = s_x[r*8+4], x5 = s_x[r*8+5];
                const float* wr = s_Wih + kk * 6;
                const float* wz = s_Wih + (256 + kk) * 6;
                const float* wn = s_Wih + (512 + kk) * 6;
                float gir = s_bih[kk]       + x0*wr[0]+x1*wr[1]+x2*wr[2]+x3*wr[3]+x4*wr[4]+x5*wr[5];
                float giz = s_bih[256 + kk] + x0*wz[0]+x1*wz[1]+x2*wz[2]+x3*wz[3]+x4*wz[4]+x5*wz[5];
                float gin = s_bih[512 + kk] + x0*wn[0]+x1*wn[1]+x2*wn[2]+x3*wn[3]+x4*wn[4]+x5*wn[5];
                float rr = sigf(gir + s_gh[r*768 + kk] + s_bhh[kk]);
                float zz = sigf(giz + s_gh[r*768 + 256 + kk] + s_bhh[256 + kk]);
                float nn = tanhfast(gin + rr * (s_gh[r*768 + 512 + kk] + s_bhh[512 + kk]));
                s_h[r*256 + kk] = (1.f - zz) * nn + zz * s_h[r*256 + kk];
            }
        }
        __syncthreads();

        // ---- out MLP for own 2 rows: 256 -> 64 -> 64 -> 6 (4-way k-split) ----
        if (tid < 512) {
            int rl = tid >> 8, kq = (tid >> 6) & 3, j = tid & 63;
            const float* hb = s_h + (half * 2 + rl) * 256 + kq * 64;
            const float* wp = s_w1 + (kq * 64) * 64 + j;
            float a0 = 0, a1 = 0;
            #pragma unroll 8
            for (int k = 0; k < 64; k += 2) {
                a0 += hb[k]     * wp[k * 64];
                a1 += hb[k + 1] * wp[(k + 1) * 64];
            }
            s_p1[(rl * 4 + kq) * 64 + j] = a0 + a1;
        }
        __syncthreads();
        if (tid < 128) {
            int rl = tid >> 6, j = tid & 63;
            const float* p = s_p1 + rl * 256 + j;
            s_o1[tid] = fmaxf(s_b1[j] + (p[0] + p[64]) + (p[128] + p[192]), 0.f);
        }
        __syncthreads();
        if (tid < 128) {
            int rl = tid >> 6, j = tid & 63;
            float a0 = 0, a1 = 0;
            #pragma unroll 8
            for (int k = 0; k < 64; k += 2) {
                a0 += s_o1[rl*64 + k]     * s_w2[k * 64 + j];
                a1 += s_o1[rl*64 + k + 1] * s_w2[(k + 1) * 64 + j];
            }
            s_o2[tid] = fmaxf(s_b2[j] + a0 + a1, 0.f);
        }
        __syncthreads();
        if (tid < 12) {
            int rl = tid / 6, a = tid % 6;
            float d0 = 0, d1 = 0;
            #pragma unroll 8
            for (int k = 0; k < 64; k += 2) {
                d0 += s_o2[rl*64 + k]     * s_w3[k * 6 + a];
                d1 += s_o2[rl*64 + k + 1] * s_w3[(k + 1) * 6 + a];
            }
            float d = s_b3[a] + d0 + d1;
            int rloc = half * 2 + rl;
            float xn = s_x[rloc * 8 + a] + d;
            s_x[rloc * 8 + a] = xn;
            int b = b0 + rloc;
            size_t o = ((size_t)b * T + t) * 6 + a;
            out[o] = d;
            out[off2 + o] = xn;
        }
        __syncthreads();
    }
}

// ---------------------------------------------------------------------------
// launch
// ---------------------------------------------------------------------------
extern "C" void kernel_launch(void* const* d_in, const int* in_sizes, int n_in,
                              void* d_out, int out_size)
{
    int hpos = -1;
    for (int i = 0; i < n_in; ++i) if (in_sizes[i] == 1) hpos = i;

    const float* ins[23];
    int j = 0;
    for (int i = 0; i < n_in && j < 23; ++i) {
        if (i == hpos) continue;
        ins[j++] = (const float*)d_in[i];
    }
    const int* hp = (hpos >= 0) ? (const int*)d_in[hpos] : nullptr;

    // ins: 0 data | 1 enc_w1 2 enc_b1 3 enc_w2 4 enc_b2 5 enc_w3 6 enc_b3
    //      7 mlp_w1 8 mlp_b1 9 mlp_w2 10 mlp_b2 11 mlp_w3 12 mlp_b3
    //      13 W_ih 14 W_hh 15 b_ih 16 b_hh
    //      17 out_w1 18 out_b1 19 out_w2 20 out_b2 21 out_w3 22 out_b3

    const int enc_smem = ENC_SMEM_FLOATS * 4;
    const int gru_smem = GRU_SMEM_FLOATS * 4;
    cudaFuncSetAttribute(enc_kernel, cudaFuncAttributeMaxDynamicSharedMemorySize, enc_smem);
    cudaFuncSetAttribute(gru_kernel, cudaFuncAttributeMaxDynamicSharedMemorySize, gru_smem);

    prep_kernel<<<1569, 256>>>(ins[14], ins[5], ins[3]);
    enc_kernel<<<dim3(8, 256), 512, enc_smem>>>(ins[0], ins[1], ins[2], ins[4], ins[6]);
    head_kernel<<<256, 512>>>(ins[7], ins[8], ins[9], ins[10], ins[11], ins[12]);
    gru_kernel<<<GRU_BLOCKS, 768, gru_smem>>>(ins[13], ins[15], ins[16],
                                              ins[17], ins[18], ins[19], ins[20], ins[21], ins[22],
                                              hp, (float*)d_out, out_size);
}